// round 14
// baseline (speedup 1.0000x reference)
#include <cuda_runtime.h>
#include <cstdint>

#define DINL __device__ __forceinline__

namespace {
constexpr int Bn = 4;
constexpr int Ln = 2048;
constexpr int DMn = 1024;
constexpr int Hn = 16;
constexpr int DHn = 64;
constexpr int MROWS = Bn * Ln;           // 8192
constexpr float LOG2E = 1.4426950408889634f;
constexpr float NEG_FILL = -1e9f;
}

// ---------------- scratch (__device__ globals; allocation-free) -------------
__device__ float g_buf0[(size_t)MROWS * DMn];      // qn, later X (attn output)
__device__ float g_qh[(size_t)Bn * Hn * Ln * DHn]; // [b][h][l][d]
__device__ float g_kh[(size_t)Bn * Hn * Ln * DHn];
__device__ float g_vh[(size_t)Bn * Hn * Ln * DHn];

// ---------------- tf32 mma helpers ------------------------------------------
DINL uint32_t f2tf(float f) {
    uint32_t r;
    asm("cvt.rna.tf32.f32 %0, %1;" : "=r"(r) : "f"(f));
    return r;
}
DINL float fast_exp2(float x) {
    float y;
    asm("ex2.approx.ftz.f32 %0, %1;" : "=f"(y) : "f"(x));
    return y;
}
DINL void mma_tf32(float& d0, float& d1, float& d2, float& d3,
                   uint32_t a0, uint32_t a1, uint32_t a2, uint32_t a3,
                   uint32_t b0, uint32_t b1) {
    asm volatile(
        "mma.sync.aligned.m16n8k8.row.col.f32.tf32.tf32.f32 "
        "{%0,%1,%2,%3}, {%4,%5,%6,%7}, {%8,%9}, {%0,%1,%2,%3};\n"
        : "+f"(d0), "+f"(d1), "+f"(d2), "+f"(d3)
        : "r"(a0), "r"(a1), "r"(a2), "r"(a3), "r"(b0), "r"(b1));
}

// ---------------- LayerNorm on q --------------------------------------------
__global__ __launch_bounds__(256) void ln_kernel(
    const float* __restrict__ q, const float* __restrict__ gamma,
    const float* __restrict__ beta, float* __restrict__ qn) {
    int row = blockIdx.x;
    int tid = threadIdx.x;
    float4 x = reinterpret_cast<const float4*>(q + (size_t)row * DMn)[tid];
    float s  = x.x + x.y + x.z + x.w;
    float s2 = x.x * x.x + x.y * x.y + x.z * x.z + x.w * x.w;
#pragma unroll
    for (int o = 16; o > 0; o >>= 1) {
        s  += __shfl_xor_sync(0xffffffffu, s, o);
        s2 += __shfl_xor_sync(0xffffffffu, s2, o);
    }
    __shared__ float ss[8], ss2[8];
    if ((tid & 31) == 0) { ss[tid >> 5] = s; ss2[tid >> 5] = s2; }
    __syncthreads();
    s = 0.f; s2 = 0.f;
#pragma unroll
    for (int i = 0; i < 8; i++) { s += ss[i]; s2 += ss2[i]; }
    float mu  = s * (1.f / 1024.f);
    float var = fmaxf(s2 * (1.f / 1024.f) - mu * mu, 0.f);
    float inv = rsqrtf(var + 1e-6f);
    float4 g4 = reinterpret_cast<const float4*>(gamma)[tid];
    float4 b4 = reinterpret_cast<const float4*>(beta)[tid];
    float4 o;
    o.x = (x.x - mu) * inv * g4.x + b4.x;
    o.y = (x.y - mu) * inv * g4.y + b4.y;
    o.z = (x.z - mu) * inv * g4.z + b4.z;
    o.w = (x.w - mu) * inv * g4.w + b4.w;
    reinterpret_cast<float4*>(qn + (size_t)row * DMn)[tid] = o;
}

// ---------------- tf32 tiled GEMM: C = A[M,1024] @ W[1024,1024] --------------
// EPI 0: write into [b][h][l][64] head layout (for Q/K/V projections)
// EPI 1: write out[m][n] = acc + RES[m][n]   (output projection + residual)
constexpr int GBM = 128, GBN = 128, GBK = 32;
constexpr int SA_STRIDE = 36;   // (4g+t)%32 distinct -> conflict-free A frags
constexpr int SB_STRIDE = 132;  // (4t+g)%32 distinct -> conflict-free B frags

template <int EPI>
DINL void epi_store2(float* __restrict__ C, const float* __restrict__ RES,
                     int m, int n, float v0, float v1) {
    if (EPI == 0) {
        int b = m >> 11;
        int l = m & (Ln - 1);
        int h = n >> 6;
        int i = n & (DHn - 1);
        size_t idx = ((size_t)(b * Hn + h) * Ln + l) * DHn + i;
        *reinterpret_cast<float2*>(C + idx) = make_float2(v0, v1);
    } else {
        size_t idx = (size_t)m * DMn + n;
        float2 r = *reinterpret_cast<const float2*>(RES + idx);
        *reinterpret_cast<float2*>(C + idx) = make_float2(v0 + r.x, v1 + r.y);
    }
}

template <int EPI>
__global__ __launch_bounds__(256) void gemm_tf32_kernel(
    const float* __restrict__ A, const float* __restrict__ W,
    float* __restrict__ C, const float* __restrict__ RES) {
    __shared__ uint32_t sA[GBM * SA_STRIDE];
    __shared__ uint32_t sB[GBK * SB_STRIDE];

    int tid = threadIdx.x;
    int bm = blockIdx.y * GBM;
    int bn = blockIdx.x * GBN;
    int wid = tid >> 5, lane = tid & 31;
    int wm = (wid & 3) * 32;   // warp m-offset (4 warps over M)
    int wn = (wid >> 2) * 64;  // warp n-offset (2 warps over N)
    int g = lane >> 2, t = lane & 3;

    float acc[2][8][4];
#pragma unroll
    for (int i = 0; i < 2; i++)
#pragma unroll
        for (int j = 0; j < 8; j++)
#pragma unroll
            for (int kq = 0; kq < 4; kq++) acc[i][j][kq] = 0.f;

    for (int kb = 0; kb < DMn; kb += GBK) {
        __syncthreads();
#pragma unroll
        for (int i = 0; i < 4; i++) {
            int pos = tid + i * 256;                 // 1024 float4 slots each
            int ar = pos >> 3, ak = (pos & 7) << 2;  // A: 128 rows x 8 float4
            float4 av = *reinterpret_cast<const float4*>(
                A + (size_t)(bm + ar) * DMn + kb + ak);
            uint32_t* da = &sA[ar * SA_STRIDE + ak];
            da[0] = f2tf(av.x); da[1] = f2tf(av.y);
            da[2] = f2tf(av.z); da[3] = f2tf(av.w);

            int br = pos >> 5, bc = (pos & 31) << 2; // B: 32 rows x 32 float4
            float4 bv = *reinterpret_cast<const float4*>(
                W + (size_t)(kb + br) * DMn + bn + bc);
            uint32_t* db = &sB[br * SB_STRIDE + bc];
            db[0] = f2tf(bv.x); db[1] = f2tf(bv.y);
            db[2] = f2tf(bv.z); db[3] = f2tf(bv.w);
        }
        __syncthreads();
#pragma unroll
        for (int kk = 0; kk < GBK; kk += 8) {
            uint32_t af[2][4];
#pragma unroll
            for (int mt = 0; mt < 2; mt++) {
                int r = wm + mt * 16;
                af[mt][0] = sA[(r + g) * SA_STRIDE + kk + t];
                af[mt][1] = sA[(r + g + 8) * SA_STRIDE + kk + t];
                af[mt][2] = sA[(r + g) * SA_STRIDE + kk + t + 4];
                af[mt][3] = sA[(r + g + 8) * SA_STRIDE + kk + t + 4];
            }
#pragma unroll
            for (int nt = 0; nt < 8; nt++) {
                uint32_t b0 = sB[(kk + t) * SB_STRIDE + wn + nt * 8 + g];
                uint32_t b1 = sB[(kk + t + 4) * SB_STRIDE + wn + nt * 8 + g];
                mma_tf32(acc[0][nt][0], acc[0][nt][1], acc[0][nt][2], acc[0][nt][3],
                         af[0][0], af[0][1], af[0][2], af[0][3], b0, b1);
                mma_tf32(acc[1][nt][0], acc[1][nt][1], acc[1][nt][2], acc[1][nt][3],
                         af[1][0], af[1][1], af[1][2], af[1][3], b0, b1);
            }
        }
    }
#pragma unroll
    for (int mt = 0; mt < 2; mt++) {
#pragma unroll
        for (int nt = 0; nt < 8; nt++) {
            int m0 = bm + wm + mt * 16 + g;
            int n0 = bn + wn + nt * 8 + 2 * t;
            epi_store2<EPI>(C, RES, m0, n0, acc[mt][nt][0], acc[mt][nt][1]);
            epi_store2<EPI>(C, RES, m0 + 8, n0, acc[mt][nt][2], acc[mt][nt][3]);
        }
    }
}

// ---------------- fused causal attention (flash-style, emits scores) --------
// block = (b*H+h, q-tile of 64); 128 threads = 4 warps x 16 q-rows.
constexpr int AQ = 64, AK = 64;
constexpr int KS = 68;  // smem stride: (4g+t)%32 distinct -> conflict-free

__global__ __launch_bounds__(128) void attn_kernel(
    const float* __restrict__ Qh, const float* __restrict__ Kh,
    const float* __restrict__ Vh, float* __restrict__ scores,
    float* __restrict__ X) {
    __shared__ uint32_t sKP[AK * KS];  // K tile, then per-warp P slabs
    __shared__ uint32_t sV[AK * KS];

    int bh = blockIdx.y;   // b*H + h
    int qt = blockIdx.x;   // q-tile index 0..31
    int q0 = qt * AQ;
    int tid = threadIdx.x, lane = tid & 31, wid = tid >> 5;
    int g = lane >> 2, t = lane & 3;
    int wr = wid * 16;

    const float* Qb = Qh + (size_t)bh * Ln * DHn;
    const float* Kb = Kh + (size_t)bh * Ln * DHn;
    const float* Vb = Vh + (size_t)bh * Ln * DHn;
    float* Srow = scores + (size_t)bh * Ln * Ln;

    // stage Q tile through sKP, pull A-fragments into registers (kept all loop)
#pragma unroll
    for (int i = 0; i < 8; i++) {
        int pos = tid + i * 128;                 // 64 rows x 16 float4
        int r = pos >> 4, c4 = (pos & 15) << 2;
        float4 v = *reinterpret_cast<const float4*>(
            Qb + (size_t)(q0 + r) * DHn + c4);
        uint32_t* d = &sKP[r * KS + c4];
        d[0] = f2tf(v.x); d[1] = f2tf(v.y); d[2] = f2tf(v.z); d[3] = f2tf(v.w);
    }
    __syncthreads();
    uint32_t qf[8][4];
#pragma unroll
    for (int kk = 0; kk < 8; kk++) {
        qf[kk][0] = sKP[(wr + g) * KS + kk * 8 + t];
        qf[kk][1] = sKP[(wr + g + 8) * KS + kk * 8 + t];
        qf[kk][2] = sKP[(wr + g) * KS + kk * 8 + t + 4];
        qf[kk][3] = sKP[(wr + g + 8) * KS + kk * 8 + t + 4];
    }

    float o[8][4];
#pragma unroll
    for (int nt = 0; nt < 8; nt++)
#pragma unroll
        for (int kq = 0; kq < 4; kq++) o[nt][kq] = 0.f;
    float m0 = -1e30f, m1 = -1e30f, l0 = 0.f, l1 = 0.f;
    int qr0 = q0 + wr + g;   // global q row for c0/c1
    int qr1 = qr0 + 8;       // global q row for c2/c3

    for (int kt = 0; kt <= qt; kt++) {
        int k0 = kt * AK;
        __syncthreads();  // everyone done with previous sKP(P)/sV
#pragma unroll
        for (int i = 0; i < 8; i++) {
            int pos = tid + i * 128;
            int r = pos >> 4, c4 = (pos & 15) << 2;
            float4 kv = *reinterpret_cast<const float4*>(
                Kb + (size_t)(k0 + r) * DHn + c4);
            float4 vv = *reinterpret_cast<const float4*>(
                Vb + (size_t)(k0 + r) * DHn + c4);
            uint32_t* dk = &sKP[r * KS + c4];
            dk[0] = f2tf(kv.x); dk[1] = f2tf(kv.y);
            dk[2] = f2tf(kv.z); dk[3] = f2tf(kv.w);
            uint32_t* dv = &sV[r * KS + c4];
            dv[0] = f2tf(vv.x); dv[1] = f2tf(vv.y);
            dv[2] = f2tf(vv.z); dv[3] = f2tf(vv.w);
        }
        __syncthreads();

        // S = Q @ K^T
        float s[8][4];
#pragma unroll
        for (int nt = 0; nt < 8; nt++)
#pragma unroll
            for (int kq = 0; kq < 4; kq++) s[nt][kq] = 0.f;
#pragma unroll
        for (int kk = 0; kk < 8; kk++) {
#pragma unroll
            for (int nt = 0; nt < 8; nt++) {
                uint32_t b0 = sKP[(nt * 8 + g) * KS + kk * 8 + t];
                uint32_t b1 = sKP[(nt * 8 + g) * KS + kk * 8 + t + 4];
                mma_tf32(s[nt][0], s[nt][1], s[nt][2], s[nt][3],
                         qf[kk][0], qf[kk][1], qf[kk][2], qf[kk][3], b0, b1);
            }
        }

        // scale, causal mask on diagonal tile, emit scores
        bool diag = (kt == qt);
#pragma unroll
        for (int nt = 0; nt < 8; nt++) {
            int kc = k0 + nt * 8 + 2 * t;
            float v0 = s[nt][0] * 0.125f, v1 = s[nt][1] * 0.125f;
            float v2 = s[nt][2] * 0.125f, v3 = s[nt][3] * 0.125f;
            if (diag) {
                if (kc > qr0) v0 = NEG_FILL;
                if (kc + 1 > qr0) v1 = NEG_FILL;
                if (kc > qr1) v2 = NEG_FILL;
                if (kc + 1 > qr1) v3 = NEG_FILL;
            }
            s[nt][0] = v0; s[nt][1] = v1; s[nt][2] = v2; s[nt][3] = v3;
            *reinterpret_cast<float2*>(Srow + (size_t)qr0 * Ln + kc) =
                make_float2(v0, v1);
            *reinterpret_cast<float2*>(Srow + (size_t)qr1 * Ln + kc) =
                make_float2(v2, v3);
        }

        // online softmax update
        float tm0 = -1e30f, tm1 = -1e30f;
#pragma unroll
        for (int nt = 0; nt < 8; nt++) {
            tm0 = fmaxf(tm0, fmaxf(s[nt][0], s[nt][1]));
            tm1 = fmaxf(tm1, fmaxf(s[nt][2], s[nt][3]));
        }
        tm0 = fmaxf(tm0, __shfl_xor_sync(0xffffffffu, tm0, 1));
        tm0 = fmaxf(tm0, __shfl_xor_sync(0xffffffffu, tm0, 2));
        tm1 = fmaxf(tm1, __shfl_xor_sync(0xffffffffu, tm1, 1));
        tm1 = fmaxf(tm1, __shfl_xor_sync(0xffffffffu, tm1, 2));
        float mn0 = fmaxf(m0, tm0), mn1 = fmaxf(m1, tm1);
        float f0 = fast_exp2((m0 - mn0) * LOG2E);
        float f1 = fast_exp2((m1 - mn1) * LOG2E);
        float ts0 = 0.f, ts1 = 0.f;
#pragma unroll
        for (int nt = 0; nt < 8; nt++) {
            float p0 = fast_exp2((s[nt][0] - mn0) * LOG2E);
            float p1 = fast_exp2((s[nt][1] - mn0) * LOG2E);
            float p2 = fast_exp2((s[nt][2] - mn1) * LOG2E);
            float p3 = fast_exp2((s[nt][3] - mn1) * LOG2E);
            ts0 += p0 + p1; ts1 += p2 + p3;
            s[nt][0] = p0; s[nt][1] = p1; s[nt][2] = p2; s[nt][3] = p3;
        }
        ts0 += __shfl_xor_sync(0xffffffffu, ts0, 1);
        ts0 += __shfl_xor_sync(0xffffffffu, ts0, 2);
        ts1 += __shfl_xor_sync(0xffffffffu, ts1, 1);
        ts1 += __shfl_xor_sync(0xffffffffu, ts1, 2);
        l0 = l0 * f0 + ts0;
        l1 = l1 * f1 + ts1;
        m0 = mn0; m1 = mn1;
#pragma unroll
        for (int nt = 0; nt < 8; nt++) {
            o[nt][0] *= f0; o[nt][1] *= f0;
            o[nt][2] *= f1; o[nt][3] *= f1;
        }

        __syncthreads();  // all warps done reading sKP as K
        // write P into this warp's 16-row slab of sKP (C-layout -> A-layout fix)
#pragma unroll
        for (int nt = 0; nt < 8; nt++) {
            int c = nt * 8 + 2 * t;
            sKP[(wr + g) * KS + c]     = f2tf(s[nt][0]);
            sKP[(wr + g) * KS + c + 1] = f2tf(s[nt][1]);
            sKP[(wr + g + 8) * KS + c]     = f2tf(s[nt][2]);
            sKP[(wr + g + 8) * KS + c + 1] = f2tf(s[nt][3]);
        }
        __syncwarp();

        // O += P @ V
#pragma unroll
        for (int kk = 0; kk < 8; kk++) {
            uint32_t a0 = sKP[(wr + g) * KS + kk * 8 + t];
            uint32_t a1 = sKP[(wr + g + 8) * KS + kk * 8 + t];
            uint32_t a2 = sKP[(wr + g) * KS + kk * 8 + t + 4];
            uint32_t a3 = sKP[(wr + g + 8) * KS + kk * 8 + t + 4];
#pragma unroll
            for (int nt = 0; nt < 8; nt++) {
                uint32_t b0 = sV[(kk * 8 + t) * KS + nt * 8 + g];
                uint32_t b1 = sV[(kk * 8 + t + 4) * KS + nt * 8 + g];
                mma_tf32(o[nt][0], o[nt][1], o[nt][2], o[nt][3],
                         a0, a1, a2, a3, b0, b1);
            }
        }
    }

    // normalize and write X in [b][l][h*64+d] layout
    float r0 = 1.f / l0, r1 = 1.f / l1;
    int bb = bh >> 4, hh = bh & 15;
#pragma unroll
    for (int nt = 0; nt < 8; nt++) {
        int d0 = nt * 8 + 2 * t;
        size_t base0 = ((size_t)bb * Ln + qr0) * DMn + hh * DHn + d0;
        size_t base1 = ((size_t)bb * Ln + qr1) * DMn + hh * DHn + d0;
        *reinterpret_cast<float2*>(X + base0) =
            make_float2(o[nt][0] * r0, o[nt][1] * r0);
        *reinterpret_cast<float2*>(X + base1) =
            make_float2(o[nt][2] * r1, o[nt][3] * r1);
    }

    // fill fully-masked upper-triangle region with exactly -1e9
    int kfill = (qt + 1) * AK;
    if (kfill < Ln) {
        int w4 = (Ln - kfill) >> 2;
        float4 fill = make_float4(NEG_FILL, NEG_FILL, NEG_FILL, NEG_FILL);
        for (int r = 0; r < AQ; r++) {
            float4* rowp = reinterpret_cast<float4*>(
                Srow + (size_t)(q0 + r) * Ln + kfill);
            for (int c = tid; c < w4; c += 128) rowp[c] = fill;
        }
    }
}

// ---------------- launch -----------------------------------------------------
extern "C" void kernel_launch(void* const* d_in, const int* in_sizes, int n_in,
                              void* d_out, int out_size) {
    (void)in_sizes; (void)n_in; (void)out_size;
    const float* q     = (const float*)d_in[0];
    const float* k     = (const float*)d_in[1];
    const float* v     = (const float*)d_in[2];
    const float* Wq    = (const float*)d_in[3];
    const float* Wk    = (const float*)d_in[4];
    const float* Wv    = (const float*)d_in[5];
    const float* Wo    = (const float*)d_in[6];
    const float* gamma = (const float*)d_in[7];
    const float* beta  = (const float*)d_in[8];

    float* buf0; float* qh; float* kh; float* vh;
    cudaGetSymbolAddress((void**)&buf0, g_buf0);
    cudaGetSymbolAddress((void**)&qh, g_qh);
    cudaGetSymbolAddress((void**)&kh, g_kh);
    cudaGetSymbolAddress((void**)&vh, g_vh);

    float* out = (float*)d_out;
    float* scores = out + (size_t)Bn * Ln * DMn;

    // 1) LayerNorm(q) -> buf0
    ln_kernel<<<MROWS, 256>>>(q, gamma, beta, buf0);

    // 2) projections -> head-major buffers
    dim3 gg(DMn / GBN, MROWS / GBM);
    gemm_tf32_kernel<0><<<gg, 256>>>(buf0, Wq, qh, nullptr);
    gemm_tf32_kernel<0><<<gg, 256>>>(k, Wk, kh, nullptr);
    gemm_tf32_kernel<0><<<gg, 256>>>(v, Wv, vh, nullptr);

    // 3) fused attention: writes scores to d_out and X to buf0
    attn_kernel<<<dim3(Ln / AQ, Bn * Hn), 128>>>(qh, kh, vh, scores, buf0);

    // 4) output projection + residual -> d_out
    gemm_tf32_kernel<1><<<gg, 256>>>(buf0, Wo, out, q);
}

// round 15
// speedup vs baseline: 1.0130x; 1.0130x over previous
#include <cuda_runtime.h>
#include <cstdint>

#define DINL __device__ __forceinline__

namespace {
constexpr int Bn = 4;
constexpr int Ln = 2048;
constexpr int DMn = 1024;
constexpr int Hn = 16;
constexpr int DHn = 64;
constexpr int MROWS = Bn * Ln;           // 8192
constexpr float LOG2E = 1.4426950408889634f;
constexpr float NEG_FILL = -1e9f;
}

// ---------------- scratch (__device__ globals; allocation-free) -------------
__device__ float g_buf0[(size_t)MROWS * DMn];      // qn, later X (attn output)
__device__ float g_qh[(size_t)Bn * Hn * Ln * DHn]; // [b][h][l][d]
__device__ float g_kh[(size_t)Bn * Hn * Ln * DHn];
__device__ float g_vh[(size_t)Bn * Hn * Ln * DHn];

// ---------------- helpers ----------------------------------------------------
DINL uint32_t smem_u32(const void* p) {
    return (uint32_t)__cvta_generic_to_shared(p);
}
DINL void cp16(uint32_t d, const void* s) {
    asm volatile("cp.async.cg.shared.global [%0], [%1], 16;\n" ::"r"(d), "l"(s));
}
DINL void cp_commit() { asm volatile("cp.async.commit_group;\n"); }
template <int N>
DINL void cp_wait() { asm volatile("cp.async.wait_group %0;\n" ::"n"(N)); }

DINL float fast_exp2(float x) {
    float y;
    asm("ex2.approx.ftz.f32 %0, %1;" : "=f"(y) : "f"(x));
    return y;
}
// raw fp32 bits into tf32 mma (HW truncates low mantissa bits)
DINL void mma_tf32(float& d0, float& d1, float& d2, float& d3,
                   uint32_t a0, uint32_t a1, uint32_t a2, uint32_t a3,
                   uint32_t b0, uint32_t b1) {
    asm volatile(
        "mma.sync.aligned.m16n8k8.row.col.f32.tf32.tf32.f32 "
        "{%0,%1,%2,%3}, {%4,%5,%6,%7}, {%8,%9}, {%0,%1,%2,%3};\n"
        : "+f"(d0), "+f"(d1), "+f"(d2), "+f"(d3)
        : "r"(a0), "r"(a1), "r"(a2), "r"(a3), "r"(b0), "r"(b1));
}

// ---------------- LayerNorm on q --------------------------------------------
__global__ __launch_bounds__(256) void ln_kernel(
    const float* __restrict__ q, const float* __restrict__ gamma,
    const float* __restrict__ beta, float* __restrict__ qn) {
    int row = blockIdx.x;
    int tid = threadIdx.x;
    float4 x = reinterpret_cast<const float4*>(q + (size_t)row * DMn)[tid];
    float s  = x.x + x.y + x.z + x.w;
    float s2 = x.x * x.x + x.y * x.y + x.z * x.z + x.w * x.w;
#pragma unroll
    for (int o = 16; o > 0; o >>= 1) {
        s  += __shfl_xor_sync(0xffffffffu, s, o);
        s2 += __shfl_xor_sync(0xffffffffu, s2, o);
    }
    __shared__ float ss[8], ss2[8];
    if ((tid & 31) == 0) { ss[tid >> 5] = s; ss2[tid >> 5] = s2; }
    __syncthreads();
    s = 0.f; s2 = 0.f;
#pragma unroll
    for (int i = 0; i < 8; i++) { s += ss[i]; s2 += ss2[i]; }
    float mu  = s * (1.f / 1024.f);
    float var = fmaxf(s2 * (1.f / 1024.f) - mu * mu, 0.f);
    float inv = rsqrtf(var + 1e-6f);
    float4 g4 = reinterpret_cast<const float4*>(gamma)[tid];
    float4 b4 = reinterpret_cast<const float4*>(beta)[tid];
    float4 o;
    o.x = (x.x - mu) * inv * g4.x + b4.x;
    o.y = (x.y - mu) * inv * g4.y + b4.y;
    o.z = (x.z - mu) * inv * g4.z + b4.z;
    o.w = (x.w - mu) * inv * g4.w + b4.w;
    reinterpret_cast<float4*>(qn + (size_t)row * DMn)[tid] = o;
}

// ---------------- tf32 GEMM, cp.async 2-stage pipeline ----------------------
// C = A[M,1024] @ W[1024,1024]; block tile 128x128, k-chunk 16.
// EPI 0: write into [b][h][l][64] head layout; EPI 1: out = acc + RES.
constexpr int GBM = 128, GBN = 128, GBK = 16;
constexpr int SA_ST = 20;   // (20g+t)%32 distinct -> conflict-free A frags
constexpr int SB_ST = 132;  // (4t+g)%32 distinct  -> conflict-free B frags

template <int EPI>
DINL void epi_store2(float* __restrict__ C, const float* __restrict__ RES,
                     int m, int n, float v0, float v1) {
    if (EPI == 0) {
        int b = m >> 11;
        int l = m & (Ln - 1);
        int h = n >> 6;
        int i = n & (DHn - 1);
        size_t idx = ((size_t)(b * Hn + h) * Ln + l) * DHn + i;
        *reinterpret_cast<float2*>(C + idx) = make_float2(v0, v1);
    } else {
        size_t idx = (size_t)m * DMn + n;
        float2 r = *reinterpret_cast<const float2*>(RES + idx);
        *reinterpret_cast<float2*>(C + idx) = make_float2(v0 + r.x, v1 + r.y);
    }
}

template <int EPI>
__global__ __launch_bounds__(256) void gemm_tf32_kernel(
    const float* __restrict__ A, const float* __restrict__ W,
    float* __restrict__ C, const float* __restrict__ RES) {
    __shared__ float sA[2][GBM * SA_ST];   // 2 x 10240 B
    __shared__ float sB[2][GBK * SB_ST];   // 2 x  8448 B

    int tid = threadIdx.x;
    int bm = blockIdx.y * GBM;
    int bn = blockIdx.x * GBN;
    int wid = tid >> 5, lane = tid & 31;
    int wm = (wid & 3) * 32;   // 4 warps over M
    int wn = (wid >> 2) * 64;  // 2 warps over N
    int g = lane >> 2, t = lane & 3;

    const float* Ag = A + (size_t)bm * DMn;
    const float* Wg = W + bn;

    float acc[2][8][4];
#pragma unroll
    for (int i = 0; i < 2; i++)
#pragma unroll
        for (int j = 0; j < 8; j++)
#pragma unroll
            for (int kq = 0; kq < 4; kq++) acc[i][j][kq] = 0.f;

    auto copy_stage = [&](int st, int kb) {
#pragma unroll
        for (int i = 0; i < 2; i++) {  // A: 128 rows x 4 float4
            int s = tid + i * 256;
            int r = s >> 2, c = (s & 3) << 2;
            cp16(smem_u32(&sA[st][r * SA_ST + c]),
                 Ag + (size_t)r * DMn + kb + c);
        }
#pragma unroll
        for (int i = 0; i < 2; i++) {  // B: 16 rows x 32 float4
            int s = tid + i * 256;
            int r = s >> 5, c = (s & 31) << 2;
            cp16(smem_u32(&sB[st][r * SB_ST + c]),
                 Wg + (size_t)(kb + r) * DMn + c);
        }
        cp_commit();
    };

    copy_stage(0, 0);
    constexpr int NK = DMn / GBK;  // 64
    for (int s = 0; s < NK; s++) {
        int st = s & 1;
        if (s + 1 < NK) {
            copy_stage(st ^ 1, (s + 1) * GBK);
            cp_wait<1>();
        } else {
            cp_wait<0>();
        }
        __syncthreads();
        const uint32_t* pA = reinterpret_cast<const uint32_t*>(sA[st]);
        const uint32_t* pB = reinterpret_cast<const uint32_t*>(sB[st]);
#pragma unroll
        for (int kk = 0; kk < GBK; kk += 8) {
            uint32_t af[2][4];
#pragma unroll
            for (int mt = 0; mt < 2; mt++) {
                int r = wm + mt * 16;
                af[mt][0] = pA[(r + g) * SA_ST + kk + t];
                af[mt][1] = pA[(r + g + 8) * SA_ST + kk + t];
                af[mt][2] = pA[(r + g) * SA_ST + kk + t + 4];
                af[mt][3] = pA[(r + g + 8) * SA_ST + kk + t + 4];
            }
#pragma unroll
            for (int nt = 0; nt < 8; nt++) {
                uint32_t b0 = pB[(kk + t) * SB_ST + wn + nt * 8 + g];
                uint32_t b1 = pB[(kk + t + 4) * SB_ST + wn + nt * 8 + g];
                mma_tf32(acc[0][nt][0], acc[0][nt][1], acc[0][nt][2], acc[0][nt][3],
                         af[0][0], af[0][1], af[0][2], af[0][3], b0, b1);
                mma_tf32(acc[1][nt][0], acc[1][nt][1], acc[1][nt][2], acc[1][nt][3],
                         af[1][0], af[1][1], af[1][2], af[1][3], b0, b1);
            }
        }
        __syncthreads();
    }
#pragma unroll
    for (int mt = 0; mt < 2; mt++) {
#pragma unroll
        for (int nt = 0; nt < 8; nt++) {
            int m0 = bm + wm + mt * 16 + g;
            int n0 = bn + wn + nt * 8 + 2 * t;
            epi_store2<EPI>(C, RES, m0, n0, acc[mt][nt][0], acc[mt][nt][1]);
            epi_store2<EPI>(C, RES, m0 + 8, n0, acc[mt][nt][2], acc[mt][nt][3]);
        }
    }
}

// ---------------- fused causal attention (flash-style, emits scores) --------
// block = (b*H+h, q-tile of 128); 256 threads = 8 warps x 16 q-rows.
// K/V tiles of 64 rows, cp.async double buffered. Dynamic smem:
//   sP  : 128 x 68 floats (Q staging, then per-warp P slabs)
//   sK/sV: 2 x 64 x 68 floats each
constexpr int AQ = 128, AK = 64;
constexpr int KS = 68;
constexpr int KV_FLOATS = AK * KS;                 // 4352
constexpr int ATT_SMEM = (AQ * KS + 4 * KV_FLOATS) * 4;  // 104448 B

__global__ __launch_bounds__(256) void attn_kernel(
    const float* __restrict__ Qh, const float* __restrict__ Kh,
    const float* __restrict__ Vh, float* __restrict__ scores,
    float* __restrict__ X) {
    extern __shared__ float sm[];
    float* sP = sm;  // 128 x 68
    float* sK[2] = {sm + AQ * KS, sm + AQ * KS + KV_FLOATS};
    float* sV[2] = {sm + AQ * KS + 2 * KV_FLOATS, sm + AQ * KS + 3 * KV_FLOATS};

    int bh = blockIdx.y;   // b*H + h
    int qt = blockIdx.x;   // 128-row q tile, 0..15
    int q0 = qt * AQ;
    int tid = threadIdx.x, lane = tid & 31, wid = tid >> 5;
    int g = lane >> 2, t = lane & 3;
    int wr = wid * 16;

    const float* Qb = Qh + (size_t)bh * Ln * DHn;
    const float* Kb = Kh + (size_t)bh * Ln * DHn;
    const float* Vb = Vh + (size_t)bh * Ln * DHn;
    float* Srow = scores + (size_t)bh * Ln * Ln;

    auto copy_kv = [&](int st, int k0) {
#pragma unroll
        for (int i = 0; i < 4; i++) {  // 64 rows x 16 float4 each matrix
            int s = tid + i * 256;
            int r = s >> 4, c = (s & 15) << 2;
            cp16(smem_u32(&sK[st][r * KS + c]), Kb + (size_t)(k0 + r) * DHn + c);
            cp16(smem_u32(&sV[st][r * KS + c]), Vb + (size_t)(k0 + r) * DHn + c);
        }
        cp_commit();
    };

    int nkt = 2 * qt + 2;  // k tiles covering kc < q0+128
    copy_kv(0, 0);

    // stage Q tile (128 x 64) into sP, then pull A-fragments into registers
#pragma unroll
    for (int i = 0; i < 8; i++) {
        int pos = tid + i * 256;
        int r = pos >> 4, c4 = (pos & 15) << 2;
        float4 v = *reinterpret_cast<const float4*>(Qb + (size_t)(q0 + r) * DHn + c4);
        *reinterpret_cast<float4*>(&sP[r * KS + c4]) = v;
    }
    __syncthreads();
    uint32_t qf[8][4];
    {
        const uint32_t* pQ = reinterpret_cast<const uint32_t*>(sP);
#pragma unroll
        for (int kk = 0; kk < 8; kk++) {
            qf[kk][0] = pQ[(wr + g) * KS + kk * 8 + t];
            qf[kk][1] = pQ[(wr + g + 8) * KS + kk * 8 + t];
            qf[kk][2] = pQ[(wr + g) * KS + kk * 8 + t + 4];
            qf[kk][3] = pQ[(wr + g + 8) * KS + kk * 8 + t + 4];
        }
    }
    __syncthreads();  // everyone holds qf before sP is reused as P slab

    float o[8][4];
#pragma unroll
    for (int nt = 0; nt < 8; nt++)
#pragma unroll
        for (int kq = 0; kq < 4; kq++) o[nt][kq] = 0.f;
    float m0 = -1e30f, m1 = -1e30f, l0 = 0.f, l1 = 0.f;
    int qr0 = q0 + wr + g;
    int qr1 = qr0 + 8;

    for (int kt = 0; kt < nkt; kt++) {
        int st = kt & 1;
        int k0 = kt * AK;
        if (kt + 1 < nkt) {
            copy_kv(st ^ 1, (kt + 1) * AK);
            cp_wait<1>();
        } else {
            cp_wait<0>();
        }
        __syncthreads();
        const uint32_t* pK = reinterpret_cast<const uint32_t*>(sK[st]);
        const uint32_t* pV = reinterpret_cast<const uint32_t*>(sV[st]);

        // S = Q @ K^T
        float s[8][4];
#pragma unroll
        for (int nt = 0; nt < 8; nt++)
#pragma unroll
            for (int kq = 0; kq < 4; kq++) s[nt][kq] = 0.f;
#pragma unroll
        for (int kk = 0; kk < 8; kk++) {
#pragma unroll
            for (int nt = 0; nt < 8; nt++) {
                uint32_t b0 = pK[(nt * 8 + g) * KS + kk * 8 + t];
                uint32_t b1 = pK[(nt * 8 + g) * KS + kk * 8 + t + 4];
                mma_tf32(s[nt][0], s[nt][1], s[nt][2], s[nt][3],
                         qf[kk][0], qf[kk][1], qf[kk][2], qf[kk][3], b0, b1);
            }
        }

        // scale, causal mask, emit scores (streaming stores)
        bool diag = (kt >= 2 * qt);
#pragma unroll
        for (int nt = 0; nt < 8; nt++) {
            int kc = k0 + nt * 8 + 2 * t;
            float v0 = s[nt][0] * 0.125f, v1 = s[nt][1] * 0.125f;
            float v2 = s[nt][2] * 0.125f, v3 = s[nt][3] * 0.125f;
            if (diag) {
                if (kc > qr0) v0 = NEG_FILL;
                if (kc + 1 > qr0) v1 = NEG_FILL;
                if (kc > qr1) v2 = NEG_FILL;
                if (kc + 1 > qr1) v3 = NEG_FILL;
            }
            s[nt][0] = v0; s[nt][1] = v1; s[nt][2] = v2; s[nt][3] = v3;
            __stcs(reinterpret_cast<float2*>(Srow + (size_t)qr0 * Ln + kc),
                   make_float2(v0, v1));
            __stcs(reinterpret_cast<float2*>(Srow + (size_t)qr1 * Ln + kc),
                   make_float2(v2, v3));
        }

        // online softmax update
        float tm0 = -1e30f, tm1 = -1e30f;
#pragma unroll
        for (int nt = 0; nt < 8; nt++) {
            tm0 = fmaxf(tm0, fmaxf(s[nt][0], s[nt][1]));
            tm1 = fmaxf(tm1, fmaxf(s[nt][2], s[nt][3]));
        }
        tm0 = fmaxf(tm0, __shfl_xor_sync(0xffffffffu, tm0, 1));
        tm0 = fmaxf(tm0, __shfl_xor_sync(0xffffffffu, tm0, 2));
        tm1 = fmaxf(tm1, __shfl_xor_sync(0xffffffffu, tm1, 1));
        tm1 = fmaxf(tm1, __shfl_xor_sync(0xffffffffu, tm1, 2));
        float mn0 = fmaxf(m0, tm0), mn1 = fmaxf(m1, tm1);
        float f0 = fast_exp2((m0 - mn0) * LOG2E);
        float f1 = fast_exp2((m1 - mn1) * LOG2E);
        float ts0 = 0.f, ts1 = 0.f;
#pragma unroll
        for (int nt = 0; nt < 8; nt++) {
            float p0 = fast_exp2((s[nt][0] - mn0) * LOG2E);
            float p1 = fast_exp2((s[nt][1] - mn0) * LOG2E);
            float p2 = fast_exp2((s[nt][2] - mn1) * LOG2E);
            float p3 = fast_exp2((s[nt][3] - mn1) * LOG2E);
            ts0 += p0 + p1; ts1 += p2 + p3;
            s[nt][0] = p0; s[nt][1] = p1; s[nt][2] = p2; s[nt][3] = p3;
        }
        ts0 += __shfl_xor_sync(0xffffffffu, ts0, 1);
        ts0 += __shfl_xor_sync(0xffffffffu, ts0, 2);
        ts1 += __shfl_xor_sync(0xffffffffu, ts1, 1);
        ts1 += __shfl_xor_sync(0xffffffffu, ts1, 2);
        l0 = l0 * f0 + ts0;
        l1 = l1 * f1 + ts1;
        m0 = mn0; m1 = mn1;
#pragma unroll
        for (int nt = 0; nt < 8; nt++) {
            o[nt][0] *= f0; o[nt][1] *= f0;
            o[nt][2] *= f1; o[nt][3] *= f1;
        }

        // write P into this warp's private 16-row slab of sP
#pragma unroll
        for (int nt = 0; nt < 8; nt++) {
            int c = nt * 8 + 2 * t;
            *reinterpret_cast<float2*>(&sP[(wr + g) * KS + c]) =
                make_float2(s[nt][0], s[nt][1]);
            *reinterpret_cast<float2*>(&sP[(wr + g + 8) * KS + c]) =
                make_float2(s[nt][2], s[nt][3]);
        }
        __syncwarp();

        // O += P @ V
        const uint32_t* pP = reinterpret_cast<const uint32_t*>(sP);
#pragma unroll
        for (int kk = 0; kk < 8; kk++) {
            uint32_t a0 = pP[(wr + g) * KS + kk * 8 + t];
            uint32_t a1 = pP[(wr + g + 8) * KS + kk * 8 + t];
            uint32_t a2 = pP[(wr + g) * KS + kk * 8 + t + 4];
            uint32_t a3 = pP[(wr + g + 8) * KS + kk * 8 + t + 4];
#pragma unroll
            for (int nt = 0; nt < 8; nt++) {
                uint32_t b0 = pV[(kk * 8 + t) * KS + nt * 8 + g];
                uint32_t b1 = pV[(kk * 8 + t + 4) * KS + nt * 8 + g];
                mma_tf32(o[nt][0], o[nt][1], o[nt][2], o[nt][3],
                         a0, a1, a2, a3, b0, b1);
            }
        }
        __syncthreads();  // done with sK[st]/sV[st] before next prefetch hits it
    }

    // normalize and write X in [b][l][h*64+d] layout
    float r0 = 1.f / l0, r1 = 1.f / l1;
    int bb = bh >> 4, hh = bh & 15;
#pragma unroll
    for (int nt = 0; nt < 8; nt++) {
        int d0 = nt * 8 + 2 * t;
        size_t base0 = ((size_t)bb * Ln + qr0) * DMn + hh * DHn + d0;
        size_t base1 = ((size_t)bb * Ln + qr1) * DMn + hh * DHn + d0;
        *reinterpret_cast<float2*>(X + base0) =
            make_float2(o[nt][0] * r0, o[nt][1] * r0);
        *reinterpret_cast<float2*>(X + base1) =
            make_float2(o[nt][2] * r1, o[nt][3] * r1);
    }

    // fill fully-masked upper-triangle region with exactly -1e9
    int kfill = (qt + 1) * AQ;
    if (kfill < Ln) {
        int w4 = (Ln - kfill) >> 2;
        float4 fill = make_float4(NEG_FILL, NEG_FILL, NEG_FILL, NEG_FILL);
        for (int r = 0; r < AQ; r++) {
            float4* rowp =
                reinterpret_cast<float4*>(Srow + (size_t)(q0 + r) * Ln + kfill);
            for (int c = tid; c < w4; c += 256) __stcs(rowp + c, fill);
        }
    }
}

// ---------------- launch -----------------------------------------------------
extern "C" void kernel_launch(void* const* d_in, const int* in_sizes, int n_in,
                              void* d_out, int out_size) {
    (void)in_sizes; (void)n_in; (void)out_size;
    const float* q     = (const float*)d_in[0];
    const float* k     = (const float*)d_in[1];
    const float* v     = (const float*)d_in[2];
    const float* Wq    = (const float*)d_in[3];
    const float* Wk    = (const float*)d_in[4];
    const float* Wv    = (const float*)d_in[5];
    const float* Wo    = (const float*)d_in[6];
    const float* gamma = (const float*)d_in[7];
    const float* beta  = (const float*)d_in[8];

    float* buf0; float* qh; float* kh; float* vh;
    cudaGetSymbolAddress((void**)&buf0, g_buf0);
    cudaGetSymbolAddress((void**)&qh, g_qh);
    cudaGetSymbolAddress((void**)&kh, g_kh);
    cudaGetSymbolAddress((void**)&vh, g_vh);

    float* out = (float*)d_out;
    float* scores = out + (size_t)Bn * Ln * DMn;

    cudaFuncSetAttribute(attn_kernel,
                         cudaFuncAttributeMaxDynamicSharedMemorySize, ATT_SMEM);

    // 1) LayerNorm(q) -> buf0
    ln_kernel<<<MROWS, 256>>>(q, gamma, beta, buf0);

    // 2) projections -> head-major buffers
    dim3 gg(DMn / GBN, MROWS / GBM);
    gemm_tf32_kernel<0><<<gg, 256>>>(buf0, Wq, qh, nullptr);
    gemm_tf32_kernel<0><<<gg, 256>>>(k, Wk, kh, nullptr);
    gemm_tf32_kernel<0><<<gg, 256>>>(v, Wv, vh, nullptr);

    // 3) fused attention: writes scores to d_out and X to buf0
    attn_kernel<<<dim3(Ln / AQ, Bn * Hn), 256, ATT_SMEM>>>(qh, kh, vh, scores, buf0);

    // 4) output projection + residual -> d_out
    gemm_tf32_kernel<1><<<gg, 256>>>(buf0, Wo, out, q);
}